// round 2
// baseline (speedup 1.0000x reference)
#include <cuda_runtime.h>
#include <cuda_bf16.h>
#include <math.h>

// ---------------------------------------------------------------------------
// Problem constants: B=2, T=2048, C=768, H=12, D=64
// ---------------------------------------------------------------------------
#define BB 2
#define TT 2048
#define CC 768
#define HH 12
#define DD 64
#define MM (BB * TT)          // 4096
#define N_QKV (3 * CC)        // 2304

// Scratch (allocation-free rule: __device__ globals)
__device__ float g_qkv[MM * N_QKV];   // [4096][2304]  q|k|v
__device__ float g_y[MM * CC];        // [4096][768]   attention output

// ---------------------------------------------------------------------------
// SGEMM + bias:  C[M,N] = A[M,K] @ B[K,N] + bias[N]
// 128x128 block tile, 8x8 per-thread, BK=8. All dims divide evenly.
// ---------------------------------------------------------------------------
#define GBM 128
#define GBN 128
#define GBK 8
#define GTM 8
#define GTN 8

__global__ __launch_bounds__(256) void sgemm_bias_kernel(
    const float* __restrict__ A, const float* __restrict__ B,
    const float* __restrict__ bias, float* __restrict__ C,
    int M, int N, int K)
{
    __shared__ float As[GBK][GBM];   // transposed A tile
    __shared__ float Bs[GBK][GBN];

    const int bx = blockIdx.x, by = blockIdx.y;
    const int tid = threadIdx.x;
    const int tcol = tid & 15;        // 0..15
    const int trow = tid >> 4;        // 0..15

    // A tile loads: 128x8 = 1024 floats, 4/thread (one float4)
    const int aRow  = tid >> 1;             // 0..127
    const int aCol4 = (tid & 1) << 2;       // 0 or 4
    // B tile loads: 8x128 = 1024 floats, 4/thread (one float4)
    const int bRow  = tid >> 5;             // 0..7
    const int bCol4 = (tid & 31) << 2;      // 0..124

    const float* Ab = A + (size_t)by * GBM * K;
    const float* Bb = B + (size_t)bx * GBN;

    float acc[GTM][GTN];
#pragma unroll
    for (int i = 0; i < GTM; i++)
#pragma unroll
        for (int j = 0; j < GTN; j++) acc[i][j] = 0.f;

    for (int k0 = 0; k0 < K; k0 += GBK) {
        float4 av = *reinterpret_cast<const float4*>(Ab + (size_t)aRow * K + k0 + aCol4);
        As[aCol4 + 0][aRow] = av.x;
        As[aCol4 + 1][aRow] = av.y;
        As[aCol4 + 2][aRow] = av.z;
        As[aCol4 + 3][aRow] = av.w;
        *reinterpret_cast<float4*>(&Bs[bRow][bCol4]) =
            *reinterpret_cast<const float4*>(Bb + (size_t)(k0 + bRow) * N + bCol4);
        __syncthreads();

#pragma unroll
        for (int kk = 0; kk < GBK; kk++) {
            float af[GTM], bf[GTN];
            float4 a0 = *reinterpret_cast<const float4*>(&As[kk][trow * GTM]);
            float4 a1 = *reinterpret_cast<const float4*>(&As[kk][trow * GTM + 4]);
            af[0]=a0.x; af[1]=a0.y; af[2]=a0.z; af[3]=a0.w;
            af[4]=a1.x; af[5]=a1.y; af[6]=a1.z; af[7]=a1.w;
            float4 b0 = *reinterpret_cast<const float4*>(&Bs[kk][tcol * GTN]);
            float4 b1 = *reinterpret_cast<const float4*>(&Bs[kk][tcol * GTN + 4]);
            bf[0]=b0.x; bf[1]=b0.y; bf[2]=b0.z; bf[3]=b0.w;
            bf[4]=b1.x; bf[5]=b1.y; bf[6]=b1.z; bf[7]=b1.w;
#pragma unroll
            for (int i = 0; i < GTM; i++)
#pragma unroll
                for (int j = 0; j < GTN; j++)
                    acc[i][j] += af[i] * bf[j];
        }
        __syncthreads();
    }

#pragma unroll
    for (int i = 0; i < GTM; i++) {
        const int gr = by * GBM + trow * GTM + i;
#pragma unroll
        for (int j = 0; j < GTN; j += 4) {
            const int gc = bx * GBN + tcol * GTN + j;
            float4 o;
            o.x = acc[i][j + 0] + bias[gc + 0];
            o.y = acc[i][j + 1] + bias[gc + 1];
            o.z = acc[i][j + 2] + bias[gc + 2];
            o.w = acc[i][j + 3] + bias[gc + 3];
            *reinterpret_cast<float4*>(C + (size_t)gr * N + gc) = o;
        }
    }
}

// ---------------------------------------------------------------------------
// Flash attention (fp32, causal).  One CTA = one (b, h, 64-row q tile).
// K tiles of 64 keys; online softmax; only kt <= qt (causal tile skipping).
// smem pitch 68 floats (272B = 16B multiple) -> float4-clean fragments.
// ---------------------------------------------------------------------------
#define AT_P 68
#define ATTN_SMEM ((4 * 64 * AT_P + 3 * 64) * (int)sizeof(float))

__global__ __launch_bounds__(256) void attn_kernel(
    const float* __restrict__ qkv, float* __restrict__ y)
{
    extern __shared__ float sm[];
    float* Qs   = sm;                   // [64][68]  Q  (row, d)
    float* Kts  = Qs  + 64 * AT_P;      // [64][68]  K^T (d, key)
    float* Vs   = Kts + 64 * AT_P;      // [64][68]  V  (key, d)
    float* Ss   = Vs  + 64 * AT_P;      // [64][68]  S/P (row, key)
    float* m_sh = Ss  + 64 * AT_P;      // [64]
    float* l_sh = m_sh + 64;            // [64]
    float* a_sh = l_sh + 64;            // [64]

    const int qt  = blockIdx.x;         // 0..31
    const int h   = blockIdx.y;         // 0..11
    const int b   = blockIdx.z;         // 0..1
    const int tid = threadIdx.x;
    const int tcol = tid & 15;
    const int trow = tid >> 4;
    const float scale = 0.125f;         // 1/sqrt(64)

    const size_t base = (size_t)b * TT * N_QKV;

    // --- load Q tile [64][64] ---
    {
        const float* Qg = qkv + base + (size_t)(qt * 64) * N_QKV + h * DD;
#pragma unroll
        for (int i = 0; i < 4; i++) {
            int f  = tid + 256 * i;       // float4 index 0..1023
            int r  = f >> 4;
            int c4 = (f & 15) << 2;
            *reinterpret_cast<float4*>(&Qs[r * AT_P + c4]) =
                *reinterpret_cast<const float4*>(Qg + (size_t)r * N_QKV + c4);
        }
    }
    if (tid < 64) { m_sh[tid] = -INFINITY; l_sh[tid] = 0.f; }

    float O[4][4];
#pragma unroll
    for (int i = 0; i < 4; i++)
#pragma unroll
        for (int j = 0; j < 4; j++) O[i][j] = 0.f;

    __syncthreads();

    for (int kt = 0; kt <= qt; kt++) {
        // --- load K (transposed) and V tiles ---
        const float* Kg = qkv + base + (size_t)(kt * 64) * N_QKV + CC + h * DD;
        const float* Vg = qkv + base + (size_t)(kt * 64) * N_QKV + 2 * CC + h * DD;
#pragma unroll
        for (int i = 0; i < 4; i++) {
            int f  = tid + 256 * i;
            int r  = f >> 4;              // key index
            int c4 = (f & 15) << 2;       // dim
            float4 kv = *reinterpret_cast<const float4*>(Kg + (size_t)r * N_QKV + c4);
            Kts[(c4 + 0) * AT_P + r] = kv.x;
            Kts[(c4 + 1) * AT_P + r] = kv.y;
            Kts[(c4 + 2) * AT_P + r] = kv.z;
            Kts[(c4 + 3) * AT_P + r] = kv.w;
            *reinterpret_cast<float4*>(&Vs[r * AT_P + c4]) =
                *reinterpret_cast<const float4*>(Vg + (size_t)r * N_QKV + c4);
        }
        __syncthreads();

        // --- S = Q @ K^T  (each thread 4x4) ---
        float s[4][4];
#pragma unroll
        for (int i = 0; i < 4; i++)
#pragma unroll
            for (int j = 0; j < 4; j++) s[i][j] = 0.f;

#pragma unroll 8
        for (int kk = 0; kk < 64; kk++) {
            float a0 = Qs[(trow * 4 + 0) * AT_P + kk];
            float a1 = Qs[(trow * 4 + 1) * AT_P + kk];
            float a2 = Qs[(trow * 4 + 2) * AT_P + kk];
            float a3 = Qs[(trow * 4 + 3) * AT_P + kk];
            float4 bv = *reinterpret_cast<const float4*>(&Kts[kk * AT_P + tcol * 4]);
            s[0][0] += a0 * bv.x; s[0][1] += a0 * bv.y; s[0][2] += a0 * bv.z; s[0][3] += a0 * bv.w;
            s[1][0] += a1 * bv.x; s[1][1] += a1 * bv.y; s[1][2] += a1 * bv.z; s[1][3] += a1 * bv.w;
            s[2][0] += a2 * bv.x; s[2][1] += a2 * bv.y; s[2][2] += a2 * bv.z; s[2][3] += a2 * bv.w;
            s[3][0] += a3 * bv.x; s[3][1] += a3 * bv.y; s[3][2] += a3 * bv.z; s[3][3] += a3 * bv.w;
        }

        // --- scale + causal mask, write S to smem ---
        const int qbase = qt * 64 + trow * 4;
        const int kbase = kt * 64 + tcol * 4;
#pragma unroll
        for (int i = 0; i < 4; i++)
#pragma unroll
            for (int j = 0; j < 4; j++) {
                float v = s[i][j] * scale;
                if (kt == qt && (kbase + j) > (qbase + i)) v = -INFINITY;
                Ss[(trow * 4 + i) * AT_P + tcol * 4 + j] = v;
            }
        __syncthreads();

        // --- online softmax per row (one thread per row) ---
        if (tid < 64) {
            const int r = tid;
            float mo = m_sh[r];
            float mt = mo;
            for (int c = 0; c < 64; c++) mt = fmaxf(mt, Ss[r * AT_P + c]);
            float alpha = __expf(mo - mt);      // 0 on first tile (mo=-inf)
            float l = l_sh[r] * alpha;
            for (int c = 0; c < 64; c++) {
                float p = __expf(Ss[r * AT_P + c] - mt);
                Ss[r * AT_P + c] = p;
                l += p;
            }
            m_sh[r] = mt; l_sh[r] = l; a_sh[r] = alpha;
        }
        __syncthreads();

        // --- O = O*alpha + P @ V ---
#pragma unroll
        for (int i = 0; i < 4; i++) {
            float alpha = a_sh[trow * 4 + i];
#pragma unroll
            for (int j = 0; j < 4; j++) O[i][j] *= alpha;
        }
#pragma unroll 8
        for (int kk = 0; kk < 64; kk++) {
            float a0 = Ss[(trow * 4 + 0) * AT_P + kk];
            float a1 = Ss[(trow * 4 + 1) * AT_P + kk];
            float a2 = Ss[(trow * 4 + 2) * AT_P + kk];
            float a3 = Ss[(trow * 4 + 3) * AT_P + kk];
            float4 bv = *reinterpret_cast<const float4*>(&Vs[kk * AT_P + tcol * 4]);
            O[0][0] += a0 * bv.x; O[0][1] += a0 * bv.y; O[0][2] += a0 * bv.z; O[0][3] += a0 * bv.w;
            O[1][0] += a1 * bv.x; O[1][1] += a1 * bv.y; O[1][2] += a1 * bv.z; O[1][3] += a1 * bv.w;
            O[2][0] += a2 * bv.x; O[2][1] += a2 * bv.y; O[2][2] += a2 * bv.z; O[2][3] += a2 * bv.w;
            O[3][0] += a3 * bv.x; O[3][1] += a3 * bv.y; O[3][2] += a3 * bv.z; O[3][3] += a3 * bv.w;
        }
        __syncthreads();   // protect Ss/Kts/Vs before next tile's loads
    }

    // --- epilogue: normalize and write to y[b][t][h*64 + d] ---
#pragma unroll
    for (int i = 0; i < 4; i++) {
        const int r = trow * 4 + i;
        const float inv = 1.0f / l_sh[r];
        const int t = qt * 64 + r;
        float4 o;
        o.x = O[i][0] * inv; o.y = O[i][1] * inv;
        o.z = O[i][2] * inv; o.w = O[i][3] * inv;
        *reinterpret_cast<float4*>(y + ((size_t)(b * TT + t) * CC) + h * DD + tcol * 4) = o;
    }
}

// ---------------------------------------------------------------------------
// Launch
// ---------------------------------------------------------------------------
extern "C" void kernel_launch(void* const* d_in, const int* in_sizes, int n_in,
                              void* d_out, int out_size)
{
    const float* x      = (const float*)d_in[0];
    const float* W_attn = (const float*)d_in[1];
    const float* b_attn = (const float*)d_in[2];
    const float* W_proj = (const float*)d_in[3];
    const float* b_proj = (const float*)d_in[4];
    float* out = (float*)d_out;

    float *qkv, *y;
    cudaGetSymbolAddress((void**)&qkv, g_qkv);
    cudaGetSymbolAddress((void**)&y, g_y);

    // 1) qkv = x @ W_attn + b_attn     [4096,768]x[768,2304]
    {
        dim3 grid(N_QKV / GBN, MM / GBM);   // (18, 32)
        sgemm_bias_kernel<<<grid, 256>>>(x, W_attn, b_attn, qkv, MM, N_QKV, CC);
    }

    // 2) flash attention -> y
    {
        cudaFuncSetAttribute(attn_kernel,
                             cudaFuncAttributeMaxDynamicSharedMemorySize, ATTN_SMEM);
        dim3 grid(TT / 64, HH, BB);         // (32, 12, 2)
        attn_kernel<<<grid, 256, ATTN_SMEM>>>(qkv, y);
    }

    // 3) out = y @ W_proj + b_proj     [4096,768]x[768,768]
    {
        dim3 grid(CC / GBN, MM / GBM);      // (6, 32)
        sgemm_bias_kernel<<<grid, 256>>>(y, W_proj, b_proj, out, MM, CC, CC);
    }
}

// round 6
// speedup vs baseline: 2.0036x; 2.0036x over previous
#include <cuda_runtime.h>
#include <cuda_bf16.h>
#include <math.h>

// Problem constants: B=2, T=2048, C=768, H=12, D=64
#define BB 2
#define TT 2048
#define CC 768
#define HH 12
#define DD 64
#define MM (BB * TT)          // 4096
#define N_QKV (3 * CC)        // 2304

__device__ float g_qkv[MM * N_QKV];
__device__ float g_y[MM * CC];

// ---------------------------------------------------------------------------
// tf32 helpers
// ---------------------------------------------------------------------------
__device__ __forceinline__ float to_tf32(float x) {
    unsigned u;
    asm("cvt.rna.tf32.f32 %0, %1;" : "=r"(u) : "f"(x));
    return __uint_as_float(u);
}

__device__ __forceinline__ void mma_tf32(float c[4],
                                         float a0, float a1, float a2, float a3,
                                         float b0, float b1) {
    unsigned ua0 = __float_as_uint(a0), ua1 = __float_as_uint(a1);
    unsigned ua2 = __float_as_uint(a2), ua3 = __float_as_uint(a3);
    unsigned ub0 = __float_as_uint(b0), ub1 = __float_as_uint(b1);
    asm volatile(
        "mma.sync.aligned.m16n8k8.row.col.f32.tf32.tf32.f32 "
        "{%0,%1,%2,%3}, {%4,%5,%6,%7}, {%8,%9}, {%0,%1,%2,%3};"
        : "+f"(c[0]), "+f"(c[1]), "+f"(c[2]), "+f"(c[3])
        : "r"(ua0), "r"(ua1), "r"(ua2), "r"(ua3), "r"(ub0), "r"(ub1));
}

// ---------------------------------------------------------------------------
// tf32 GEMM + bias:  C[M,N] = A[M,K] @ B[K,N] + bias[N]
// 128x128x16 tile, 256 threads (8 warps), warp tile 32x64 (2x8 mma tiles)
// ---------------------------------------------------------------------------
#define BM 128
#define BN 128
#define BKT 16
#define AP 20     // As pitch (floats): conflict-free (20 mod 32 = 20, rows spread)
#define BP 132    // Bs pitch (floats): 132 mod 32 = 4 -> conflict-free frag reads

__global__ __launch_bounds__(256) void gemm_tf32_bias(
    const float* __restrict__ A, const float* __restrict__ B,
    const float* __restrict__ bias, float* __restrict__ C,
    int M, int N, int K)
{
    __shared__ float As[BM * AP];   // [m][k] tf32-rounded
    __shared__ float Bs[BKT * BP];  // [k][n] tf32-rounded

    const int bx = blockIdx.x, by = blockIdx.y;
    const int tid = threadIdx.x;
    const int lane = tid & 31;
    const int wid = tid >> 5;
    const int warp_m = wid & 3;        // 0..3 -> 32 rows each
    const int warp_n = wid >> 2;       // 0..1 -> 64 cols each
    const int lq = lane >> 2;          // groupID 0..7
    const int lr = lane & 3;           // 0..3

    // gmem tile load mapping
    const int aRow = tid >> 1;             // 0..127
    const int aCol = (tid & 1) << 3;       // 0 or 8
    const int bRow = tid >> 4;             // 0..15
    const int bCol = (tid & 15) << 3;      // 0..120

    const float* Ab = A + (size_t)by * BM * K;
    const float* Bb = B + (size_t)bx * BN;

    float acc[2][8][4];
#pragma unroll
    for (int i = 0; i < 2; i++)
#pragma unroll
        for (int j = 0; j < 8; j++)
#pragma unroll
            for (int q = 0; q < 4; q++) acc[i][j][q] = 0.f;

    for (int k0 = 0; k0 < K; k0 += BKT) {
        float4 av0 = *reinterpret_cast<const float4*>(Ab + (size_t)aRow * K + k0 + aCol);
        float4 av1 = *reinterpret_cast<const float4*>(Ab + (size_t)aRow * K + k0 + aCol + 4);
        float4 bv0 = *reinterpret_cast<const float4*>(Bb + (size_t)(k0 + bRow) * N + bCol);
        float4 bv1 = *reinterpret_cast<const float4*>(Bb + (size_t)(k0 + bRow) * N + bCol + 4);
        __syncthreads();
        {
            float4 t0, t1;
            t0.x = to_tf32(av0.x); t0.y = to_tf32(av0.y); t0.z = to_tf32(av0.z); t0.w = to_tf32(av0.w);
            t1.x = to_tf32(av1.x); t1.y = to_tf32(av1.y); t1.z = to_tf32(av1.z); t1.w = to_tf32(av1.w);
            *reinterpret_cast<float4*>(&As[aRow * AP + aCol]) = t0;
            *reinterpret_cast<float4*>(&As[aRow * AP + aCol + 4]) = t1;
            t0.x = to_tf32(bv0.x); t0.y = to_tf32(bv0.y); t0.z = to_tf32(bv0.z); t0.w = to_tf32(bv0.w);
            t1.x = to_tf32(bv1.x); t1.y = to_tf32(bv1.y); t1.z = to_tf32(bv1.z); t1.w = to_tf32(bv1.w);
            *reinterpret_cast<float4*>(&Bs[bRow * BP + bCol]) = t0;
            *reinterpret_cast<float4*>(&Bs[bRow * BP + bCol + 4]) = t1;
        }
        __syncthreads();

#pragma unroll
        for (int ks = 0; ks < BKT; ks += 8) {
            float af[2][4], bf[8][2];
#pragma unroll
            for (int mt = 0; mt < 2; mt++) {
                const int mb = warp_m * 32 + mt * 16;
                af[mt][0] = As[(mb + lq) * AP + ks + lr];
                af[mt][1] = As[(mb + lq + 8) * AP + ks + lr];
                af[mt][2] = As[(mb + lq) * AP + ks + lr + 4];
                af[mt][3] = As[(mb + lq + 8) * AP + ks + lr + 4];
            }
#pragma unroll
            for (int nt = 0; nt < 8; nt++) {
                const int nb = warp_n * 64 + nt * 8;
                bf[nt][0] = Bs[(ks + lr) * BP + nb + lq];
                bf[nt][1] = Bs[(ks + lr + 4) * BP + nb + lq];
            }
#pragma unroll
            for (int mt = 0; mt < 2; mt++)
#pragma unroll
                for (int nt = 0; nt < 8; nt++)
                    mma_tf32(acc[mt][nt], af[mt][0], af[mt][1], af[mt][2], af[mt][3],
                             bf[nt][0], bf[nt][1]);
        }
    }

    // epilogue with bias
#pragma unroll
    for (int mt = 0; mt < 2; mt++) {
        const int r0 = by * BM + warp_m * 32 + mt * 16 + lq;
#pragma unroll
        for (int nt = 0; nt < 8; nt++) {
            const int gc = bx * BN + warp_n * 64 + nt * 8 + lr * 2;
            float2 bia = *reinterpret_cast<const float2*>(bias + gc);
            float2 o0, o1;
            o0.x = acc[mt][nt][0] + bia.x; o0.y = acc[mt][nt][1] + bia.y;
            o1.x = acc[mt][nt][2] + bia.x; o1.y = acc[mt][nt][3] + bia.y;
            *reinterpret_cast<float2*>(C + (size_t)r0 * N + gc) = o0;
            *reinterpret_cast<float2*>(C + (size_t)(r0 + 8) * N + gc) = o1;
        }
    }
}

// ---------------------------------------------------------------------------
// Flash attention, tf32 tensor cores. CTA = (b, h, 64-q-row tile), 128 threads.
// Warp w owns q-rows 16w..16w+15. S/P round-trips through smem for softmax.
// ---------------------------------------------------------------------------
#define AT_P 68   // 68 mod 32 = 4 -> conflict-free fragment reads
#define ATTN_SMEM ((4 * 64 * AT_P + 3 * 64) * (int)sizeof(float))

__global__ __launch_bounds__(128) void attn_kernel(
    const float* __restrict__ qkv, float* __restrict__ y)
{
    extern __shared__ float sm[];
    float* Qs   = sm;                   // [64][68]  Q (row, d)     tf32
    float* Kts  = Qs  + 64 * AT_P;      // [64][68]  K^T (d, key)   tf32
    float* Vs   = Kts + 64 * AT_P;      // [64][68]  V (key, d)     tf32
    float* Ss   = Vs  + 64 * AT_P;      // [64][68]  S / P          fp32
    float* m_sh = Ss  + 64 * AT_P;
    float* l_sh = m_sh + 64;
    float* a_sh = l_sh + 64;

    const int qt  = blockIdx.x;
    const int h   = blockIdx.y;
    const int b   = blockIdx.z;
    const int tid = threadIdx.x;
    const int lane = tid & 31;
    const int w    = tid >> 5;          // warp 0..3
    const int lq = lane >> 2;           // 0..7
    const int lr = lane & 3;            // 0..3
    const float scale = 0.125f;

    const size_t base = (size_t)b * TT * N_QKV;

    // load Q tile [64][64] -> tf32
    {
        const float* Qg = qkv + base + (size_t)(qt * 64) * N_QKV + h * DD;
#pragma unroll
        for (int i = 0; i < 8; i++) {
            int f = tid + 128 * i;          // float4 idx 0..1023
            int r = f >> 4, c4 = (f & 15) << 2;
            float4 v = *reinterpret_cast<const float4*>(Qg + (size_t)r * N_QKV + c4);
            v.x = to_tf32(v.x); v.y = to_tf32(v.y); v.z = to_tf32(v.z); v.w = to_tf32(v.w);
            *reinterpret_cast<float4*>(&Qs[r * AT_P + c4]) = v;
        }
    }
    if (tid < 64) { m_sh[tid] = -INFINITY; l_sh[tid] = 0.f; }

    float O[8][4];
#pragma unroll
    for (int i = 0; i < 8; i++)
#pragma unroll
        for (int j = 0; j < 4; j++) O[i][j] = 0.f;

    __syncthreads();

    for (int kt = 0; kt <= qt; kt++) {
        const float* Kg = qkv + base + (size_t)(kt * 64) * N_QKV + CC + h * DD;
        const float* Vg = qkv + base + (size_t)(kt * 64) * N_QKV + 2 * CC + h * DD;
#pragma unroll
        for (int i = 0; i < 8; i++) {
            int f = tid + 128 * i;
            int r = f >> 4, c4 = (f & 15) << 2;   // r = key, c4 = dim
            float4 kv = *reinterpret_cast<const float4*>(Kg + (size_t)r * N_QKV + c4);
            Kts[(c4 + 0) * AT_P + r] = to_tf32(kv.x);
            Kts[(c4 + 1) * AT_P + r] = to_tf32(kv.y);
            Kts[(c4 + 2) * AT_P + r] = to_tf32(kv.z);
            Kts[(c4 + 3) * AT_P + r] = to_tf32(kv.w);
            float4 vv = *reinterpret_cast<const float4*>(Vg + (size_t)r * N_QKV + c4);
            vv.x = to_tf32(vv.x); vv.y = to_tf32(vv.y); vv.z = to_tf32(vv.z); vv.w = to_tf32(vv.w);
            *reinterpret_cast<float4*>(&Vs[r * AT_P + c4]) = vv;
        }
        __syncthreads();

        // ---- S = Q @ K^T (warp mma: 16 rows x 64 keys) ----
        float sacc[8][4];
#pragma unroll
        for (int nt = 0; nt < 8; nt++)
#pragma unroll
            for (int q = 0; q < 4; q++) sacc[nt][q] = 0.f;

#pragma unroll
        for (int ks = 0; ks < 64; ks += 8) {
            const int mb = w * 16;
            float a0 = Qs[(mb + lq) * AT_P + ks + lr];
            float a1 = Qs[(mb + lq + 8) * AT_P + ks + lr];
            float a2 = Qs[(mb + lq) * AT_P + ks + lr + 4];
            float a3 = Qs[(mb + lq + 8) * AT_P + ks + lr + 4];
#pragma unroll
            for (int nt = 0; nt < 8; nt++) {
                float b0 = Kts[(ks + lr) * AT_P + nt * 8 + lq];
                float b1 = Kts[(ks + lr + 4) * AT_P + nt * 8 + lq];
                mma_tf32(sacc[nt], a0, a1, a2, a3, b0, b1);
            }
        }

        // scale + causal mask (in regs), store to Ss
        {
            const int row0 = qt * 64 + w * 16 + lq;
            const int row1 = row0 + 8;
#pragma unroll
            for (int nt = 0; nt < 8; nt++) {
                const int col = kt * 64 + nt * 8 + lr * 2;
                float v0 = sacc[nt][0] * scale, v1 = sacc[nt][1] * scale;
                float v2 = sacc[nt][2] * scale, v3 = sacc[nt][3] * scale;
                if (kt == qt) {
                    if (col     > row0) v0 = -INFINITY;
                    if (col + 1 > row0) v1 = -INFINITY;
                    if (col     > row1) v2 = -INFINITY;
                    if (col + 1 > row1) v3 = -INFINITY;
                }
                const int sr0 = w * 16 + lq;
                const int sc  = nt * 8 + lr * 2;
                *reinterpret_cast<float2*>(&Ss[sr0 * AT_P + sc]) = make_float2(v0, v1);
                *reinterpret_cast<float2*>(&Ss[(sr0 + 8) * AT_P + sc]) = make_float2(v2, v3);
            }
        }
        __syncthreads();

        // ---- online softmax (one thread per row) ----
        if (tid < 64) {
            const int r = tid;
            float mo = m_sh[r];
            float mt = mo;
            for (int c = 0; c < 64; c++) mt = fmaxf(mt, Ss[r * AT_P + c]);
            float alpha = __expf(mo - mt);
            float l = l_sh[r] * alpha;
            for (int c = 0; c < 64; c++) {
                float p = to_tf32(__expf(Ss[r * AT_P + c] - mt));
                Ss[r * AT_P + c] = p;
                l += p;
            }
            m_sh[r] = mt; l_sh[r] = l; a_sh[r] = alpha;
        }
        __syncthreads();

        // ---- O = O*alpha + P @ V (warp mma) ----
        {
            const float alpha0 = a_sh[w * 16 + lq];
            const float alpha1 = a_sh[w * 16 + lq + 8];
#pragma unroll
            for (int nt = 0; nt < 8; nt++) {
                O[nt][0] *= alpha0; O[nt][1] *= alpha0;
                O[nt][2] *= alpha1; O[nt][3] *= alpha1;
            }
        }
#pragma unroll
        for (int ks = 0; ks < 64; ks += 8) {
            const int mb = w * 16;
            float a0 = Ss[(mb + lq) * AT_P + ks + lr];
            float a1 = Ss[(mb + lq + 8) * AT_P + ks + lr];
            float a2 = Ss[(mb + lq) * AT_P + ks + lr + 4];
            float a3 = Ss[(mb + lq + 8) * AT_P + ks + lr + 4];
#pragma unroll
            for (int nt = 0; nt < 8; nt++) {
                float b0 = Vs[(ks + lr) * AT_P + nt * 8 + lq];
                float b1 = Vs[(ks + lr + 4) * AT_P + nt * 8 + lq];
                mma_tf32(O[nt], a0, a1, a2, a3, b0, b1);
            }
        }
        __syncthreads();   // protect Kts/Vs/Ss before next tile loads
    }

    // epilogue: normalize, write y[b][t][h*64+d]
    {
        const int r0 = w * 16 + lq;
        const int r1 = r0 + 8;
        const float inv0 = 1.0f / l_sh[r0];
        const float inv1 = 1.0f / l_sh[r1];
        const int t0 = qt * 64 + r0;
        const int t1 = qt * 64 + r1;
#pragma unroll
        for (int nt = 0; nt < 8; nt++) {
            const int c = h * DD + nt * 8 + lr * 2;
            float2 o0 = make_float2(O[nt][0] * inv0, O[nt][1] * inv0);
            float2 o1 = make_float2(O[nt][2] * inv1, O[nt][3] * inv1);
            *reinterpret_cast<float2*>(y + (size_t)(b * TT + t0) * CC + c) = o0;
            *reinterpret_cast<float2*>(y + (size_t)(b * TT + t1) * CC + c) = o1;
        }
    }
}

// ---------------------------------------------------------------------------
// Launch
// ---------------------------------------------------------------------------
extern "C" void kernel_launch(void* const* d_in, const int* in_sizes, int n_in,
                              void* d_out, int out_size)
{
    const float* x      = (const float*)d_in[0];
    const float* W_attn = (const float*)d_in[1];
    const float* b_attn = (const float*)d_in[2];
    const float* W_proj = (const float*)d_in[3];
    const float* b_proj = (const float*)d_in[4];
    float* out = (float*)d_out;

    float *qkv, *y;
    cudaGetSymbolAddress((void**)&qkv, g_qkv);
    cudaGetSymbolAddress((void**)&y, g_y);

    // 1) qkv = x @ W_attn + b_attn
    {
        dim3 grid(N_QKV / BN, MM / BM);   // (18, 32)
        gemm_tf32_bias<<<grid, 256>>>(x, W_attn, b_attn, qkv, MM, N_QKV, CC);
    }

    // 2) flash attention -> y
    {
        cudaFuncSetAttribute(attn_kernel,
                             cudaFuncAttributeMaxDynamicSharedMemorySize, ATTN_SMEM);
        dim3 grid(TT / 64, HH, BB);       // (32, 12, 2)
        attn_kernel<<<grid, 128, ATTN_SMEM>>>(qkv, y);
    }

    // 3) out = y @ W_proj + b_proj
    {
        dim3 grid(CC / BN, MM / BM);      // (6, 32)
        gemm_tf32_bias<<<grid, 256>>>(y, W_proj, b_proj, out, MM, CC, CC);
    }
}

// round 8
// speedup vs baseline: 2.4509x; 1.2233x over previous
#include <cuda_runtime.h>
#include <cuda_bf16.h>
#include <math.h>

// Problem constants: B=2, T=2048, C=768, H=12, D=64
#define BB 2
#define TT 2048
#define CC 768
#define HH 12
#define DD 64
#define MM (BB * TT)          // 4096
#define N_QKV (3 * CC)        // 2304

__device__ float g_qkv[MM * N_QKV];
__device__ float g_y[MM * CC];

// ---------------------------------------------------------------------------
// tf32 helpers
// ---------------------------------------------------------------------------
__device__ __forceinline__ float to_tf32(float x) {
    unsigned u;
    asm("cvt.rna.tf32.f32 %0, %1;" : "=r"(u) : "f"(x));
    return __uint_as_float(u);
}

__device__ __forceinline__ void mma_tf32(float c[4],
                                         float a0, float a1, float a2, float a3,
                                         float b0, float b1) {
    unsigned ua0 = __float_as_uint(a0), ua1 = __float_as_uint(a1);
    unsigned ua2 = __float_as_uint(a2), ua3 = __float_as_uint(a3);
    unsigned ub0 = __float_as_uint(b0), ub1 = __float_as_uint(b1);
    asm volatile(
        "mma.sync.aligned.m16n8k8.row.col.f32.tf32.tf32.f32 "
        "{%0,%1,%2,%3}, {%4,%5,%6,%7}, {%8,%9}, {%0,%1,%2,%3};"
        : "+f"(c[0]), "+f"(c[1]), "+f"(c[2]), "+f"(c[3])
        : "r"(ua0), "r"(ua1), "r"(ua2), "r"(ua3), "r"(ub0), "r"(ub1));
}

// ---------------------------------------------------------------------------
// tf32 GEMM + bias, double-buffered smem + gmem prefetch.
// 128x128x16 tile, 256 threads (8 warps), warp tile 32x64 (2x8 mma tiles)
// ---------------------------------------------------------------------------
#define BM 128
#define BN 128
#define BKT 16
#define AP 20
#define BP 132

__global__ __launch_bounds__(256) void gemm_tf32_bias(
    const float* __restrict__ A, const float* __restrict__ B,
    const float* __restrict__ bias, float* __restrict__ C,
    int M, int N, int K)
{
    __shared__ float As[2][BM * AP];
    __shared__ float Bs[2][BKT * BP];

    const int bx = blockIdx.x, by = blockIdx.y;
    const int tid = threadIdx.x;
    const int lane = tid & 31;
    const int wid = tid >> 5;
    const int warp_m = wid & 3;
    const int warp_n = wid >> 2;
    const int lq = lane >> 2;
    const int lr = lane & 3;

    const int aRow = tid >> 1;
    const int aCol = (tid & 1) << 3;
    const int bRow = tid >> 4;
    const int bCol = (tid & 15) << 3;

    const float* Ab = A + (size_t)by * BM * K;
    const float* Bb = B + (size_t)bx * BN;

    float acc[2][8][4];
#pragma unroll
    for (int i = 0; i < 2; i++)
#pragma unroll
        for (int j = 0; j < 8; j++)
#pragma unroll
            for (int q = 0; q < 4; q++) acc[i][j][q] = 0.f;

    // prologue: stage k0 = 0
    {
        float4 av0 = *reinterpret_cast<const float4*>(Ab + (size_t)aRow * K + aCol);
        float4 av1 = *reinterpret_cast<const float4*>(Ab + (size_t)aRow * K + aCol + 4);
        float4 bv0 = *reinterpret_cast<const float4*>(Bb + (size_t)bRow * N + bCol);
        float4 bv1 = *reinterpret_cast<const float4*>(Bb + (size_t)bRow * N + bCol + 4);
        float4 t;
        t.x = to_tf32(av0.x); t.y = to_tf32(av0.y); t.z = to_tf32(av0.z); t.w = to_tf32(av0.w);
        *reinterpret_cast<float4*>(&As[0][aRow * AP + aCol]) = t;
        t.x = to_tf32(av1.x); t.y = to_tf32(av1.y); t.z = to_tf32(av1.z); t.w = to_tf32(av1.w);
        *reinterpret_cast<float4*>(&As[0][aRow * AP + aCol + 4]) = t;
        t.x = to_tf32(bv0.x); t.y = to_tf32(bv0.y); t.z = to_tf32(bv0.z); t.w = to_tf32(bv0.w);
        *reinterpret_cast<float4*>(&Bs[0][bRow * BP + bCol]) = t;
        t.x = to_tf32(bv1.x); t.y = to_tf32(bv1.y); t.z = to_tf32(bv1.z); t.w = to_tf32(bv1.w);
        *reinterpret_cast<float4*>(&Bs[0][bRow * BP + bCol + 4]) = t;
    }
    __syncthreads();

    int cur = 0;
    for (int k0 = 0; k0 < K; k0 += BKT) {
        const bool has_next = (k0 + BKT) < K;
        float4 nav0, nav1, nbv0, nbv1;
        if (has_next) {
            const int kn = k0 + BKT;
            nav0 = *reinterpret_cast<const float4*>(Ab + (size_t)aRow * K + kn + aCol);
            nav1 = *reinterpret_cast<const float4*>(Ab + (size_t)aRow * K + kn + aCol + 4);
            nbv0 = *reinterpret_cast<const float4*>(Bb + (size_t)(kn + bRow) * N + bCol);
            nbv1 = *reinterpret_cast<const float4*>(Bb + (size_t)(kn + bRow) * N + bCol + 4);
        }

        const float* Asc = As[cur];
        const float* Bsc = Bs[cur];
#pragma unroll
        for (int ks = 0; ks < BKT; ks += 8) {
            float af[2][4], bf[8][2];
#pragma unroll
            for (int mt = 0; mt < 2; mt++) {
                const int mb = warp_m * 32 + mt * 16;
                af[mt][0] = Asc[(mb + lq) * AP + ks + lr];
                af[mt][1] = Asc[(mb + lq + 8) * AP + ks + lr];
                af[mt][2] = Asc[(mb + lq) * AP + ks + lr + 4];
                af[mt][3] = Asc[(mb + lq + 8) * AP + ks + lr + 4];
            }
#pragma unroll
            for (int nt = 0; nt < 8; nt++) {
                const int nb = warp_n * 64 + nt * 8;
                bf[nt][0] = Bsc[(ks + lr) * BP + nb + lq];
                bf[nt][1] = Bsc[(ks + lr + 4) * BP + nb + lq];
            }
#pragma unroll
            for (int mt = 0; mt < 2; mt++)
#pragma unroll
                for (int nt = 0; nt < 8; nt++)
                    mma_tf32(acc[mt][nt], af[mt][0], af[mt][1], af[mt][2], af[mt][3],
                             bf[nt][0], bf[nt][1]);
        }

        if (has_next) {
            float* Asn = As[cur ^ 1];
            float* Bsn = Bs[cur ^ 1];
            float4 t;
            t.x = to_tf32(nav0.x); t.y = to_tf32(nav0.y); t.z = to_tf32(nav0.z); t.w = to_tf32(nav0.w);
            *reinterpret_cast<float4*>(&Asn[aRow * AP + aCol]) = t;
            t.x = to_tf32(nav1.x); t.y = to_tf32(nav1.y); t.z = to_tf32(nav1.z); t.w = to_tf32(nav1.w);
            *reinterpret_cast<float4*>(&Asn[aRow * AP + aCol + 4]) = t;
            t.x = to_tf32(nbv0.x); t.y = to_tf32(nbv0.y); t.z = to_tf32(nbv0.z); t.w = to_tf32(nbv0.w);
            *reinterpret_cast<float4*>(&Bsn[bRow * BP + bCol]) = t;
            t.x = to_tf32(nbv1.x); t.y = to_tf32(nbv1.y); t.z = to_tf32(nbv1.z); t.w = to_tf32(nbv1.w);
            *reinterpret_cast<float4*>(&Bsn[bRow * BP + bCol + 4]) = t;
        }
        __syncthreads();
        cur ^= 1;
    }

    // epilogue with bias
#pragma unroll
    for (int mt = 0; mt < 2; mt++) {
        const int r0 = by * BM + warp_m * 32 + mt * 16 + lq;
#pragma unroll
        for (int nt = 0; nt < 8; nt++) {
            const int gc = bx * BN + warp_n * 64 + nt * 8 + lr * 2;
            float2 bia = *reinterpret_cast<const float2*>(bias + gc);
            float2 o0, o1;
            o0.x = acc[mt][nt][0] + bia.x; o0.y = acc[mt][nt][1] + bia.y;
            o1.x = acc[mt][nt][2] + bia.x; o1.y = acc[mt][nt][3] + bia.y;
            *reinterpret_cast<float2*>(C + (size_t)r0 * N + gc) = o0;
            *reinterpret_cast<float2*>(C + (size_t)(r0 + 8) * N + gc) = o1;
        }
    }
}

// ---------------------------------------------------------------------------
// Flash attention, tf32 tensor cores, register-resident online softmax.
// CTA = (b, h, 64-q-row tile), 128 threads (4 warps, 16 q-rows each).
// K kept row-major (B-fragment reads directly); Q fragments hoisted to regs.
// Smem: Ks, Vs, Ss (Ss doubles as Q staging). 52.2 KB -> 4 CTAs/SM.
// ---------------------------------------------------------------------------
#define AT_P 68
#define ATTN_SMEM (3 * 64 * AT_P * (int)sizeof(float))

__global__ __launch_bounds__(128) void attn_kernel(
    const float* __restrict__ qkv, float* __restrict__ y)
{
    extern __shared__ float sm[];
    float* Ks = sm;                    // [64][68] K (key, d) tf32
    float* Vs = Ks + 64 * AT_P;        // [64][68] V (key, d) tf32
    float* Ss = Vs + 64 * AT_P;        // [64][68] Q staging, then P

    const int qt  = blockIdx.x;
    const int h   = blockIdx.y;
    const int b   = blockIdx.z;
    const int tid = threadIdx.x;
    const int lane = tid & 31;
    const int w    = tid >> 5;
    const int lq = lane >> 2;          // 0..7
    const int lr = lane & 3;           // 0..3
    const float scale = 0.125f;

    const size_t base = (size_t)b * TT * N_QKV;

    // ---- stage Q into Ss, then hoist fragments into registers ----
    {
        const float* Qg = qkv + base + (size_t)(qt * 64) * N_QKV + h * DD;
#pragma unroll
        for (int i = 0; i < 8; i++) {
            int f = tid + 128 * i;
            int r = f >> 4, c4 = (f & 15) << 2;
            float4 v = *reinterpret_cast<const float4*>(Qg + (size_t)r * N_QKV + c4);
            v.x = to_tf32(v.x); v.y = to_tf32(v.y); v.z = to_tf32(v.z); v.w = to_tf32(v.w);
            *reinterpret_cast<float4*>(&Ss[r * AT_P + c4]) = v;
        }
    }
    __syncthreads();

    float qf[8][4];
#pragma unroll
    for (int ks8 = 0; ks8 < 8; ks8++) {
        const int k = ks8 * 8;
        const int mb = w * 16;
        qf[ks8][0] = Ss[(mb + lq) * AT_P + k + lr];
        qf[ks8][1] = Ss[(mb + lq + 8) * AT_P + k + lr];
        qf[ks8][2] = Ss[(mb + lq) * AT_P + k + lr + 4];
        qf[ks8][3] = Ss[(mb + lq + 8) * AT_P + k + lr + 4];
    }

    float m0 = -INFINITY, m1 = -INFINITY, l0 = 0.f, l1 = 0.f;
    float O[8][4];
#pragma unroll
    for (int i = 0; i < 8; i++)
#pragma unroll
        for (int j = 0; j < 4; j++) O[i][j] = 0.f;

    for (int kt = 0; kt <= qt; kt++) {
        __syncthreads();   // prior iter's Ss/Vs reads (or Q frag loads) complete

        // ---- load K, V tiles (row-major, tf32) ----
        const float* Kg = qkv + base + (size_t)(kt * 64) * N_QKV + CC + h * DD;
        const float* Vg = qkv + base + (size_t)(kt * 64) * N_QKV + 2 * CC + h * DD;
#pragma unroll
        for (int i = 0; i < 8; i++) {
            int f = tid + 128 * i;
            int r = f >> 4, c4 = (f & 15) << 2;
            float4 kv = *reinterpret_cast<const float4*>(Kg + (size_t)r * N_QKV + c4);
            kv.x = to_tf32(kv.x); kv.y = to_tf32(kv.y); kv.z = to_tf32(kv.z); kv.w = to_tf32(kv.w);
            *reinterpret_cast<float4*>(&Ks[r * AT_P + c4]) = kv;
            float4 vv = *reinterpret_cast<const float4*>(Vg + (size_t)r * N_QKV + c4);
            vv.x = to_tf32(vv.x); vv.y = to_tf32(vv.y); vv.z = to_tf32(vv.z); vv.w = to_tf32(vv.w);
            *reinterpret_cast<float4*>(&Vs[r * AT_P + c4]) = vv;
        }
        __syncthreads();

        // ---- S = Q @ K^T ----
        float sacc[8][4];
#pragma unroll
        for (int nt = 0; nt < 8; nt++)
#pragma unroll
            for (int q = 0; q < 4; q++) sacc[nt][q] = 0.f;

#pragma unroll
        for (int ks8 = 0; ks8 < 8; ks8++) {
            const int k = ks8 * 8;
#pragma unroll
            for (int nt = 0; nt < 8; nt++) {
                float b0 = Ks[(nt * 8 + lq) * AT_P + k + lr];
                float b1 = Ks[(nt * 8 + lq) * AT_P + k + lr + 4];
                mma_tf32(sacc[nt], qf[ks8][0], qf[ks8][1], qf[ks8][2], qf[ks8][3], b0, b1);
            }
        }

        // ---- scale + causal mask in registers ----
        {
            const int row0 = qt * 64 + w * 16 + lq;
            const int row1 = row0 + 8;
#pragma unroll
            for (int nt = 0; nt < 8; nt++) {
                const int col = kt * 64 + nt * 8 + lr * 2;
                sacc[nt][0] *= scale; sacc[nt][1] *= scale;
                sacc[nt][2] *= scale; sacc[nt][3] *= scale;
                if (kt == qt) {
                    if (col     > row0) sacc[nt][0] = -INFINITY;
                    if (col + 1 > row0) sacc[nt][1] = -INFINITY;
                    if (col     > row1) sacc[nt][2] = -INFINITY;
                    if (col + 1 > row1) sacc[nt][3] = -INFINITY;
                }
            }
        }

        // ---- register online softmax (rows on 4 lanes sharing lq) ----
        float mt0 = -INFINITY, mt1 = -INFINITY;
#pragma unroll
        for (int nt = 0; nt < 8; nt++) {
            mt0 = fmaxf(mt0, fmaxf(sacc[nt][0], sacc[nt][1]));
            mt1 = fmaxf(mt1, fmaxf(sacc[nt][2], sacc[nt][3]));
        }
        mt0 = fmaxf(mt0, __shfl_xor_sync(0xffffffffu, mt0, 1));
        mt0 = fmaxf(mt0, __shfl_xor_sync(0xffffffffu, mt0, 2));
        mt1 = fmaxf(mt1, __shfl_xor_sync(0xffffffffu, mt1, 1));
        mt1 = fmaxf(mt1, __shfl_xor_sync(0xffffffffu, mt1, 2));

        const float mn0 = fmaxf(m0, mt0);
        const float mn1 = fmaxf(m1, mt1);
        const float al0 = __expf(m0 - mn0);
        const float al1 = __expf(m1 - mn1);
        m0 = mn0; m1 = mn1;

        float s0 = 0.f, s1 = 0.f;
        {
            const int sr0 = w * 16 + lq;
            const int sc  = lr * 2;
#pragma unroll
            for (int nt = 0; nt < 8; nt++) {
                float p00 = __expf(sacc[nt][0] - mn0);
                float p01 = __expf(sacc[nt][1] - mn0);
                float p10 = __expf(sacc[nt][2] - mn1);
                float p11 = __expf(sacc[nt][3] - mn1);
                s0 += p00 + p01;
                s1 += p10 + p11;
                *reinterpret_cast<float2*>(&Ss[sr0 * AT_P + nt * 8 + sc]) =
                    make_float2(to_tf32(p00), to_tf32(p01));
                *reinterpret_cast<float2*>(&Ss[(sr0 + 8) * AT_P + nt * 8 + sc]) =
                    make_float2(to_tf32(p10), to_tf32(p11));
            }
        }
        s0 += __shfl_xor_sync(0xffffffffu, s0, 1);
        s0 += __shfl_xor_sync(0xffffffffu, s0, 2);
        s1 += __shfl_xor_sync(0xffffffffu, s1, 1);
        s1 += __shfl_xor_sync(0xffffffffu, s1, 2);
        l0 = l0 * al0 + s0;
        l1 = l1 * al1 + s1;

        // ---- rescale O, then O += P @ V ----
#pragma unroll
        for (int nt = 0; nt < 8; nt++) {
            O[nt][0] *= al0; O[nt][1] *= al0;
            O[nt][2] *= al1; O[nt][3] *= al1;
        }
        __syncwarp();   // P produced and consumed within the same warp

#pragma unroll
        for (int ks8 = 0; ks8 < 8; ks8++) {
            const int k = ks8 * 8;
            const int mb = w * 16;
            float a0 = Ss[(mb + lq) * AT_P + k + lr];
            float a1 = Ss[(mb + lq + 8) * AT_P + k + lr];
            float a2 = Ss[(mb + lq) * AT_P + k + lr + 4];
            float a3 = Ss[(mb + lq + 8) * AT_P + k + lr + 4];
#pragma unroll
            for (int nt = 0; nt < 8; nt++) {
                float b0 = Vs[(k + lr) * AT_P + nt * 8 + lq];
                float b1 = Vs[(k + lr + 4) * AT_P + nt * 8 + lq];
                mma_tf32(O[nt], a0, a1, a2, a3, b0, b1);
            }
        }
    }

    // ---- epilogue: normalize, write y[b][t][h*64+d] ----
    {
        const float inv0 = 1.0f / l0;
        const float inv1 = 1.0f / l1;
        const int t0 = qt * 64 + w * 16 + lq;
        const int t1 = t0 + 8;
#pragma unroll
        for (int nt = 0; nt < 8; nt++) {
            const int c = h * DD + nt * 8 + lr * 2;
            float2 o0 = make_float2(O[nt][0] * inv0, O[nt][1] * inv0);
            float2 o1 = make_float2(O[nt][2] * inv1, O[nt][3] * inv1);
            *reinterpret_cast<float2*>(y + (size_t)(b * TT + t0) * CC + c) = o0;
            *reinterpret_cast<float2*>(y + (size_t)(b * TT + t1) * CC + c) = o1;
        }
    }
}

// ---------------------------------------------------------------------------
// Launch
// ---------------------------------------------------------------------------
extern "C" void kernel_launch(void* const* d_in, const int* in_sizes, int n_in,
                              void* d_out, int out_size)
{
    const float* x      = (const float*)d_in[0];
    const float* W_attn = (const float*)d_in[1];
    const float* b_attn = (const float*)d_in[2];
    const float* W_proj = (const float*)d_in[3];
    const float* b_proj = (const float*)d_in[4];
    float* out = (float*)d_out;

    float *qkv, *y;
    cudaGetSymbolAddress((void**)&qkv, g_qkv);
    cudaGetSymbolAddress((void**)&y, g_y);

    // 1) qkv = x @ W_attn + b_attn
    {
        dim3 grid(N_QKV / BN, MM / BM);   // (18, 32)
        gemm_tf32_bias<<<grid, 256>>>(x, W_attn, b_attn, qkv, MM, N_QKV, CC);
    }

    // 2) flash attention -> y
    {
        cudaFuncSetAttribute(attn_kernel,
                             cudaFuncAttributeMaxDynamicSharedMemorySize, ATTN_SMEM);
        dim3 grid(TT / 64, HH, BB);       // (32, 12, 2)
        attn_kernel<<<grid, 128, ATTN_SMEM>>>(qkv, y);
    }

    // 3) out = y @ W_proj + b_proj
    {
        dim3 grid(CC / BN, MM / BM);      // (6, 32)
        gemm_tf32_bias<<<grid, 256>>>(y, W_proj, b_proj, out, MM, CC, CC);
    }
}